// round 3
// baseline (speedup 1.0000x reference)
#include <cuda_runtime.h>
#include <math.h>

#define DD     2048
#define NS     16
#define NP     8               // packed mode pairs
#define BB     2
#define LL     4096
#define NCHAN  (BB * DD)
#define CHUNK  (LL / 32)

typedef unsigned long long u64;

__device__ __forceinline__ u64 pk2(float lo, float hi) {
    u64 r; asm("mov.b64 %0, {%1,%2};" : "=l"(r) : "f"(lo), "f"(hi)); return r;
}
__device__ __forceinline__ void upk2(u64 v, float& lo, float& hi) {
    asm("mov.b64 {%0,%1}, %2;" : "=f"(lo), "=f"(hi) : "l"(v));
}
__device__ __forceinline__ u64 ffma2(u64 a, u64 b, u64 c) {
    u64 d; asm("fma.rn.f32x2 %0, %1, %2, %3;" : "=l"(d) : "l"(a), "l"(b), "l"(c)); return d;
}
__device__ __forceinline__ u64 fmul2(u64 a, u64 b) {
    u64 d; asm("mul.rn.f32x2 %0, %1, %2;" : "=l"(d) : "l"(a), "l"(b)); return d;
}
__device__ __forceinline__ u64 fadd2(u64 a, u64 b) {
    u64 d; asm("add.rn.f32x2 %0, %1, %2;" : "=l"(d) : "l"(a), "l"(b)); return d;
}
__device__ __forceinline__ float sigm(float v) {
    return 1.0f / (1.0f + expf(-v));
}

__global__ __launch_bounds__(256) void cema_kernel(
    const float* __restrict__ x,      // (B, D, L)
    const float* __restrict__ alpha,  // (D, N)
    const float* __restrict__ delta,  // (D, N)
    const float* __restrict__ theta,  // (D)
    const float* __restrict__ gamma,  // (D, N, 2)
    const float* __restrict__ omega,  // (D)
    float* __restrict__ out)          // y (B,D,L) then h (B,D,N,2)
{
    const int warp = (blockIdx.x * blockDim.x + threadIdx.x) >> 5;
    const int lane = threadIdx.x & 31;
    if (warp >= NCHAN) return;
    const int d = warp & (DD - 1);

    const float base = sigm(theta[d]) * (6.283185307179586f / 16.0f);
    const float om   = omega[d];

    // ---- biquad denominator coeffs: a1 = 2*Re(q), a2 = -|q|^2 = -mag^2 ----
    u64 A1[NP], A2[NP];
    #pragma unroll
    for (int j = 0; j < NP; j++) {
        float a1v[2], a2v[2];
        #pragma unroll
        for (int h = 0; h < 2; h++) {
            int n = 2 * j + h;
            float p   = sigm(alpha[d * NS + n]);
            float de  = sigm(delta[d * NS + n]);
            float mag = 1.0f - p * de;
            float s, c;
            sincosf((float)(n + 1) * base, &s, &c);
            a1v[h] = 2.0f * (mag * c);
            a2v[h] = -(mag * mag);
        }
        A1[j] = pk2(a1v[0], a1v[1]);
        A2[j] = pk2(a2v[0], a2v[1]);
    }

    const size_t chbase = (size_t)warp * LL;
    const float4* __restrict__ xc4 =
        (const float4*)(x + chbase + (size_t)lane * CHUNK);

    // ---- Phase 1: local biquad scan from zero state (W = w[t], Wp = w[t-1]) ----
    u64 W[NP], Wp[NP];
    #pragma unroll
    for (int j = 0; j < NP; j++) { W[j] = 0ull; Wp[j] = 0ull; }

    #pragma unroll 1
    for (int i4 = 0; i4 < CHUNK / 4; i4++) {
        float4 xv = xc4[i4];
        float xs[4] = { xv.x, xv.y, xv.z, xv.w };
        #pragma unroll
        for (int k = 0; k < 4; k++) {
            u64 X = pk2(xs[k], xs[k]);
            #pragma unroll
            for (int j = 0; j < NP; j++) {
                u64 wn = ffma2(A1[j], W[j], ffma2(A2[j], Wp[j], X));
                Wp[j] = W[j]; W[j] = wn;
            }
        }
    }

    // ---- M = companion^CHUNK, companion = [[a1,a2],[1,0]], 7 squarings ----
    u64 M00[NP], M01[NP], M10[NP], M11[NP];
    const u64 ONE2 = pk2(1.0f, 1.0f);
    #pragma unroll
    for (int j = 0; j < NP; j++) {
        M00[j] = A1[j]; M01[j] = A2[j]; M10[j] = ONE2; M11[j] = 0ull;
    }
    #pragma unroll
    for (int s = 0; s < 7; s++) {
        #pragma unroll
        for (int j = 0; j < NP; j++) {
            u64 tr = fadd2(M00[j], M11[j]);
            u64 t  = fmul2(M01[j], M10[j]);
            u64 n00 = ffma2(M00[j], M00[j], t);
            u64 n11 = ffma2(M11[j], M11[j], t);
            M01[j] = fmul2(M01[j], tr);
            M10[j] = fmul2(M10[j], tr);
            M00[j] = n00; M11[j] = n11;
        }
    }

    // ---- inclusive Hillis-Steele scan: v <- M * v_prev + v ----
    #pragma unroll
    for (int k = 1; k <= 16; k <<= 1) {
        #pragma unroll
        for (int j = 0; j < NP; j++) {
            u64 tw  = __shfl_up_sync(0xFFFFFFFFu, W[j],  k);
            u64 twp = __shfl_up_sync(0xFFFFFFFFu, Wp[j], k);
            if (lane >= k) {
                u64 nw = ffma2(M00[j], tw, ffma2(M01[j], twp, W[j]));
                u64 np = ffma2(M10[j], tw, ffma2(M11[j], twp, Wp[j]));
                W[j] = nw; Wp[j] = np;
            }
        }
        if (k < 16) {
            #pragma unroll
            for (int j = 0; j < NP; j++) {
                u64 tr = fadd2(M00[j], M11[j]);
                u64 t  = fmul2(M01[j], M10[j]);
                u64 n00 = ffma2(M00[j], M00[j], t);
                u64 n11 = ffma2(M11[j], M11[j], t);
                M01[j] = fmul2(M01[j], tr);
                M10[j] = fmul2(M10[j], tr);
                M00[j] = n00; M11[j] = n11;
            }
        }
    }

    // ---- numerator coeffs b0 = Re(c), b1 = -Re(c*conj(q)); h from lane 31.
    //      S[L-1] = w[L-1] - conj(q)*w[L-2]  ->  h = p*S[L-1]. ----
    u64 B0[NP], B1[NP];
    float* hptr = out + (size_t)BB * DD * LL + (size_t)warp * NS * 2;
    #pragma unroll
    for (int j = 0; j < NP; j++) {
        float b0v[2], b1v[2];
        float wlo, whi, plo, phi2;
        upk2(W[j],  wlo, whi);
        upk2(Wp[j], plo, phi2);
        float wv2[2]  = { wlo, whi };
        float wpv2[2] = { plo, phi2 };
        #pragma unroll
        for (int h = 0; h < 2; h++) {
            int n = 2 * j + h;
            float p   = sigm(alpha[d * NS + n]);
            float de  = sigm(delta[d * NS + n]);
            float mag = 1.0f - p * de;
            float s, c;
            sincosf((float)(n + 1) * base, &s, &c);
            float qr = mag * c, qi = mag * s;
            float cr = p * gamma[(d * NS + n) * 2 + 0] * 0.25f;
            float ci = p * gamma[(d * NS + n) * 2 + 1] * 0.25f;
            b0v[h] = cr;
            b1v[h] = -(cr * qr + ci * qi);
            if (lane == 31) {
                hptr[2 * n + 0] = p * (wv2[h] - qr * wpv2[h]);
                hptr[2 * n + 1] = p * (qi * wpv2[h]);
            }
        }
        B0[j] = pk2(b0v[0], b0v[1]);
        B1[j] = pk2(b1v[0], b1v[1]);
    }

    // ---- incoming state per chunk = exclusive scan (shift by 1) ----
    #pragma unroll
    for (int j = 0; j < NP; j++) {
        u64 tw  = __shfl_up_sync(0xFFFFFFFFu, W[j],  1);
        u64 twp = __shfl_up_sync(0xFFFFFFFFu, Wp[j], 1);
        W[j]  = (lane == 0) ? 0ull : tw;
        Wp[j] = (lane == 0) ? 0ull : twp;
    }

    // ---- Phase 2: rescan with correct init, emit y ----
    float4* __restrict__ yc4 = (float4*)(out + chbase + (size_t)lane * CHUNK);
    #pragma unroll 1
    for (int i4 = 0; i4 < CHUNK / 4; i4++) {
        float4 xv = xc4[i4];
        float xs[4] = { xv.x, xv.y, xv.z, xv.w };
        float ys[4];
        #pragma unroll
        for (int k = 0; k < 4; k++) {
            float xk = xs[k];
            u64 X = pk2(xk, xk);
            u64 acc0 = pk2(xk * om, 0.0f);
            u64 acc1 = 0ull, acc2 = 0ull, acc3 = 0ull;
            #pragma unroll
            for (int j = 0; j < NP; j++) {
                u64 wn = ffma2(A1[j], W[j], ffma2(A2[j], Wp[j], X));
                u64& acc = (j & 3) == 0 ? acc0 : (j & 3) == 1 ? acc1
                         : (j & 3) == 2 ? acc2 : acc3;
                acc = ffma2(B0[j], wn,   acc);
                acc = ffma2(B1[j], W[j], acc);   // b1 * w[t-1]
                Wp[j] = W[j]; W[j] = wn;
            }
            u64 s = fadd2(fadd2(acc0, acc1), fadd2(acc2, acc3));
            float lo, hi;
            upk2(s, lo, hi);
            ys[k] = lo + hi;
        }
        yc4[i4] = make_float4(ys[0], ys[1], ys[2], ys[3]);
    }
}

extern "C" void kernel_launch(void* const* d_in, const int* in_sizes, int n_in,
                              void* d_out, int out_size)
{
    const float* x     = (const float*)d_in[0];
    const float* alpha = (const float*)d_in[1];
    const float* delta = (const float*)d_in[2];
    const float* theta = (const float*)d_in[3];
    const float* gamma = (const float*)d_in[4];
    const float* omega = (const float*)d_in[5];
    float* out = (float*)d_out;

    const int threads = 256;
    const int blocks  = (NCHAN * 32) / threads;
    cema_kernel<<<blocks, threads>>>(x, alpha, delta, theta, gamma, omega, out);
}

// round 5
// speedup vs baseline: 1.2698x; 1.2698x over previous
#include <cuda_runtime.h>
#include <math.h>

#define DD     2048
#define NS     16
#define BB     2
#define LL     4096
#define NCHAN  (BB * DD)
#define CHUNK  (LL / 32)

__device__ __forceinline__ float sigm(float v) {
    return 1.0f / (1.0f + expf(-v));
}

__global__ __launch_bounds__(256) void cema_kernel(
    const float* __restrict__ x,      // (B, D, L)
    const float* __restrict__ alpha,  // (D, N)
    const float* __restrict__ delta,  // (D, N)
    const float* __restrict__ theta,  // (D)
    const float* __restrict__ gamma,  // (D, N, 2)
    const float* __restrict__ omega,  // (D)
    float* __restrict__ out)          // y (B,D,L) then h (B,D,N,2)
{
    const int warp = (blockIdx.x * blockDim.x + threadIdx.x) >> 5;
    const int lane = threadIdx.x & 31;
    if (warp >= NCHAN) return;
    const int d = warp & (DD - 1);

    const float base = sigm(theta[d]) * (6.283185307179586f / 16.0f);
    const float om   = omega[d];

    // ---- biquad denominator coeffs: a1 = 2*Re(q), a2 = -|q|^2.
    //      qsign bit n = 1 iff sin(phi_n) < 0 (needed to recover signed qi later). ----
    float A1[NS], A2[NS];
    unsigned qsign = 0u;
    #pragma unroll
    for (int n = 0; n < NS; n++) {
        float p   = sigm(alpha[d * NS + n]);
        float de  = sigm(delta[d * NS + n]);
        float mag = 1.0f - p * de;
        float s, c;
        sincosf((float)(n + 1) * base, &s, &c);
        if (s < 0.0f) qsign |= (1u << n);
        A1[n] = 2.0f * (mag * c);
        A2[n] = -(mag * mag);
    }

    const size_t chbase = (size_t)warp * LL;
    const float4* __restrict__ xc4 =
        (const float4*)(x + chbase + (size_t)lane * CHUNK);

    // ---- Phase 1: local biquad scan from zero (W = w[t], Wp = w[t-1]) ----
    float W[NS], Wp[NS];
    #pragma unroll
    for (int n = 0; n < NS; n++) { W[n] = 0.0f; Wp[n] = 0.0f; }

    #pragma unroll 1
    for (int i4 = 0; i4 < CHUNK / 4; i4++) {
        float4 xv = xc4[i4];
        float xs[4] = { xv.x, xv.y, xv.z, xv.w };
        #pragma unroll
        for (int k = 0; k < 4; k++) {
            float xk = xs[k];
            #pragma unroll
            for (int n = 0; n < NS; n++) {
                float wn = fmaf(A1[n], W[n], fmaf(A2[n], Wp[n], xk));
                Wp[n] = W[n]; W[n] = wn;
            }
        }
    }

    // ---- M = companion^CHUNK, companion = [[a1,a2],[1,0]], 7 squarings ----
    {
        float M00[NS], M01[NS], M10[NS], M11[NS];
        #pragma unroll
        for (int n = 0; n < NS; n++) {
            M00[n] = A1[n]; M01[n] = A2[n]; M10[n] = 1.0f; M11[n] = 0.0f;
        }
        #pragma unroll
        for (int s = 0; s < 7; s++) {
            #pragma unroll
            for (int n = 0; n < NS; n++) {
                float tr = M00[n] + M11[n];
                float t  = M01[n] * M10[n];
                float n00 = fmaf(M00[n], M00[n], t);
                float n11 = fmaf(M11[n], M11[n], t);
                M01[n] *= tr;
                M10[n] *= tr;
                M00[n] = n00; M11[n] = n11;
            }
        }

        // ---- inclusive Hillis-Steele scan: v <- M * v_prev + v ----
        #pragma unroll
        for (int k = 1; k <= 16; k <<= 1) {
            #pragma unroll
            for (int n = 0; n < NS; n++) {
                float tw  = __shfl_up_sync(0xFFFFFFFFu, W[n],  k);
                float twp = __shfl_up_sync(0xFFFFFFFFu, Wp[n], k);
                if (lane >= k) {
                    float nw = fmaf(M00[n], tw, fmaf(M01[n], twp, W[n]));
                    float np = fmaf(M10[n], tw, fmaf(M11[n], twp, Wp[n]));
                    W[n] = nw; Wp[n] = np;
                }
            }
            if (k < 16) {
                #pragma unroll
                for (int n = 0; n < NS; n++) {
                    float tr = M00[n] + M11[n];
                    float t  = M01[n] * M10[n];
                    float n00 = fmaf(M00[n], M00[n], t);
                    float n11 = fmaf(M11[n], M11[n], t);
                    M01[n] *= tr;
                    M10[n] *= tr;
                    M00[n] = n00; M11[n] = n11;
                }
            }
        }
    }   // M dies here

    // ---- h from lane 31: recover q from (a1, a2) + sign bit.
    //      qr = a1/2, |qi| = sqrt(-a2 - qr^2), qi = sign ? -|qi| : |qi|.
    //      S[L-1] = w[L-1] - conj(q)*w[L-2]; h = p * S[L-1]. ----
    if (lane == 31) {
        float* hptr = out + (size_t)BB * DD * LL + (size_t)warp * NS * 2;
        #pragma unroll
        for (int n = 0; n < NS; n++) {
            float qr = 0.5f * A1[n];
            float qi = sqrtf(fmaxf(fmaf(-qr, qr, -A2[n]), 0.0f));
            if (qsign & (1u << n)) qi = -qi;
            float p  = sigm(alpha[d * NS + n]);
            hptr[2 * n + 0] = p * fmaf(-qr, Wp[n], W[n]);
            hptr[2 * n + 1] = p * (qi * Wp[n]);
        }
    }

    // ---- incoming state per chunk = exclusive scan (shift by 1) ----
    #pragma unroll
    for (int n = 0; n < NS; n++) {
        float tw  = __shfl_up_sync(0xFFFFFFFFu, W[n],  1);
        float twp = __shfl_up_sync(0xFFFFFFFFu, Wp[n], 1);
        W[n]  = (lane == 0) ? 0.0f : tw;
        Wp[n] = (lane == 0) ? 0.0f : twp;
    }

    // ---- numerator coeffs: b0 = Re(c), b1 = -Re(c*conj(q)),
    //      with signed qi recovered from (a1,a2,sign bit). ----
    float B0[NS], B1[NS];
    #pragma unroll
    for (int n = 0; n < NS; n++) {
        float qr = 0.5f * A1[n];
        float qi = sqrtf(fmaxf(fmaf(-qr, qr, -A2[n]), 0.0f));
        if (qsign & (1u << n)) qi = -qi;
        float p  = sigm(alpha[d * NS + n]);
        float cr = p * gamma[(d * NS + n) * 2 + 0] * 0.25f;
        float ci = p * gamma[(d * NS + n) * 2 + 1] * 0.25f;
        B0[n] = cr;
        B1[n] = -fmaf(cr, qr, ci * qi);
    }

    // ---- Phase 2: rescan with correct init, emit y ----
    float4* __restrict__ yc4 = (float4*)(out + chbase + (size_t)lane * CHUNK);
    #pragma unroll 1
    for (int i4 = 0; i4 < CHUNK / 4; i4++) {
        float4 xv = xc4[i4];
        float xs[4] = { xv.x, xv.y, xv.z, xv.w };
        float ys[4];
        #pragma unroll
        for (int k = 0; k < 4; k++) {
            float xk = xs[k];
            float acc0 = xk * om;
            float acc1 = 0.0f, acc2 = 0.0f, acc3 = 0.0f;
            #pragma unroll
            for (int n = 0; n < NS; n++) {
                float wn = fmaf(A1[n], W[n], fmaf(A2[n], Wp[n], xk));
                float& acc = (n & 3) == 0 ? acc0 : (n & 3) == 1 ? acc1
                           : (n & 3) == 2 ? acc2 : acc3;
                acc = fmaf(B0[n], wn,   acc);
                acc = fmaf(B1[n], W[n], acc);    // b1 * w[t-1]
                Wp[n] = W[n]; W[n] = wn;
            }
            ys[k] = (acc0 + acc1) + (acc2 + acc3);
        }
        yc4[i4] = make_float4(ys[0], ys[1], ys[2], ys[3]);
    }
}

extern "C" void kernel_launch(void* const* d_in, const int* in_sizes, int n_in,
                              void* d_out, int out_size)
{
    const float* x     = (const float*)d_in[0];
    const float* alpha = (const float*)d_in[1];
    const float* delta = (const float*)d_in[2];
    const float* theta = (const float*)d_in[3];
    const float* gamma = (const float*)d_in[4];
    const float* omega = (const float*)d_in[5];
    float* out = (float*)d_out;

    const int threads = 256;
    const int blocks  = (NCHAN * 32) / threads;
    cema_kernel<<<blocks, threads>>>(x, alpha, delta, theta, gamma, omega, out);
}

// round 6
// speedup vs baseline: 1.7513x; 1.3791x over previous
#include <cuda_runtime.h>
#include <math.h>

#define DD     2048
#define NS     16
#define BB     2
#define LL     4096
#define NCHAN  (BB * DD)
#define CHUNK  (LL / 32)

__device__ __forceinline__ float sigm(float v) {
    return 1.0f / (1.0f + expf(-v));
}

__global__ __launch_bounds__(128, 3) void cema_kernel(
    const float* __restrict__ x,      // (B, D, L)
    const float* __restrict__ alpha,  // (D, N)
    const float* __restrict__ delta,  // (D, N)
    const float* __restrict__ theta,  // (D)
    const float* __restrict__ gamma,  // (D, N, 2)
    const float* __restrict__ omega,  // (D)
    float* __restrict__ out)          // y (B,D,L) then h (B,D,N,2)
{
    const int warp = (blockIdx.x * blockDim.x + threadIdx.x) >> 5;
    const int lane = threadIdx.x & 31;
    if (warp >= NCHAN) return;
    const int d = warp & (DD - 1);

    const float base = sigm(theta[d]) * (6.283185307179586f / 16.0f);
    const float om   = omega[d];

    // ---- biquad denominator coeffs: a1 = 2*Re(q), a2 = -|q|^2.
    //      qsign bit n = 1 iff sin(phi_n) < 0. ----
    float A1[NS], A2[NS];
    unsigned qsign = 0u;
    #pragma unroll
    for (int n = 0; n < NS; n++) {
        float p   = sigm(alpha[d * NS + n]);
        float de  = sigm(delta[d * NS + n]);
        float mag = 1.0f - p * de;
        float s, c;
        sincosf((float)(n + 1) * base, &s, &c);
        if (s < 0.0f) qsign |= (1u << n);
        A1[n] = 2.0f * (mag * c);
        A2[n] = -(mag * mag);
    }

    const size_t chbase = (size_t)warp * LL;
    const float4* __restrict__ xc4 =
        (const float4*)(x + chbase + (size_t)lane * CHUNK);

    // ---- Phase 1: local biquad scan from zero (W = w[t], Wp = w[t-1]),
    //      8 steps per iteration, 2-deep float4 prefetch (MLP=2). ----
    float W[NS], Wp[NS];
    #pragma unroll
    for (int n = 0; n < NS; n++) { W[n] = 0.0f; Wp[n] = 0.0f; }

    {
        float4 c0 = xc4[0], c1 = xc4[1];
        #pragma unroll 1
        for (int i = 0; i < 16; i++) {
            int j = (i < 15) ? 2 * i + 2 : 30;
            float4 n0 = xc4[j], n1 = xc4[j + 1];
            float xs[8] = { c0.x, c0.y, c0.z, c0.w, c1.x, c1.y, c1.z, c1.w };
            #pragma unroll
            for (int k = 0; k < 8; k++) {
                float xk = xs[k];
                #pragma unroll
                for (int n = 0; n < NS; n++) {
                    float wn = fmaf(A1[n], W[n], fmaf(A2[n], Wp[n], xk));
                    Wp[n] = W[n]; W[n] = wn;
                }
            }
            c0 = n0; c1 = n1;
        }
    }

    // ---- chunk transition + warp scan, modes in groups of 4 so only
    //      16 M-registers are live at once (peak-register control).
    //      M = companion^128 via 7 squarings; scan level k uses M^(k). ----
    #pragma unroll
    for (int g = 0; g < 4; g++) {
        float m00[4], m01[4], m10[4], m11[4];
        #pragma unroll
        for (int u = 0; u < 4; u++) {
            int n = 4 * g + u;
            m00[u] = A1[n]; m01[u] = A2[n]; m10[u] = 1.0f; m11[u] = 0.0f;
        }
        #pragma unroll
        for (int s = 0; s < 7; s++) {
            #pragma unroll
            for (int u = 0; u < 4; u++) {
                float tr = m00[u] + m11[u];
                float t  = m01[u] * m10[u];
                float n00 = fmaf(m00[u], m00[u], t);
                float n11 = fmaf(m11[u], m11[u], t);
                m01[u] *= tr; m10[u] *= tr;
                m00[u] = n00; m11[u] = n11;
            }
        }
        #pragma unroll
        for (int k = 1; k <= 16; k <<= 1) {
            #pragma unroll
            for (int u = 0; u < 4; u++) {
                int n = 4 * g + u;
                float tw  = __shfl_up_sync(0xFFFFFFFFu, W[n],  k);
                float twp = __shfl_up_sync(0xFFFFFFFFu, Wp[n], k);
                if (lane >= k) {
                    float nw = fmaf(m00[u], tw, fmaf(m01[u], twp, W[n]));
                    float np = fmaf(m10[u], tw, fmaf(m11[u], twp, Wp[n]));
                    W[n] = nw; Wp[n] = np;
                }
            }
            if (k < 16) {
                #pragma unroll
                for (int u = 0; u < 4; u++) {
                    float tr = m00[u] + m11[u];
                    float t  = m01[u] * m10[u];
                    float n00 = fmaf(m00[u], m00[u], t);
                    float n11 = fmaf(m11[u], m11[u], t);
                    m01[u] *= tr; m10[u] *= tr;
                    m00[u] = n00; m11[u] = n11;
                }
            }
        }
    }

    // ---- h from lane 31: qr = a1/2, |qi| = sqrt(-a2 - qr^2), signed by qsign.
    //      S[L-1] = w[L-1] - conj(q)*w[L-2]; h = p * S[L-1]. ----
    if (lane == 31) {
        float* hptr = out + (size_t)BB * DD * LL + (size_t)warp * NS * 2;
        #pragma unroll
        for (int n = 0; n < NS; n++) {
            float qr = 0.5f * A1[n];
            float qi = sqrtf(fmaxf(fmaf(-qr, qr, -A2[n]), 0.0f));
            if (qsign & (1u << n)) qi = -qi;
            float p  = sigm(alpha[d * NS + n]);
            hptr[2 * n + 0] = p * fmaf(-qr, Wp[n], W[n]);
            hptr[2 * n + 1] = p * (qi * Wp[n]);
        }
    }

    // ---- incoming state per chunk = exclusive scan (shift by 1) ----
    #pragma unroll
    for (int n = 0; n < NS; n++) {
        float tw  = __shfl_up_sync(0xFFFFFFFFu, W[n],  1);
        float twp = __shfl_up_sync(0xFFFFFFFFu, Wp[n], 1);
        W[n]  = (lane == 0) ? 0.0f : tw;
        Wp[n] = (lane == 0) ? 0.0f : twp;
    }

    // ---- numerator coeffs: b0 = Re(c), b1 = -Re(c*conj(q)) ----
    float B0[NS], B1[NS];
    #pragma unroll
    for (int n = 0; n < NS; n++) {
        float qr = 0.5f * A1[n];
        float qi = sqrtf(fmaxf(fmaf(-qr, qr, -A2[n]), 0.0f));
        if (qsign & (1u << n)) qi = -qi;
        float p  = sigm(alpha[d * NS + n]);
        float cr = p * gamma[(d * NS + n) * 2 + 0] * 0.25f;
        float ci = p * gamma[(d * NS + n) * 2 + 1] * 0.25f;
        B0[n] = cr;
        B1[n] = -fmaf(cr, qr, ci * qi);
    }

    // ---- Phase 2: rescan with correct init, emit y; same prefetch shape ----
    float4* __restrict__ yc4 = (float4*)(out + chbase + (size_t)lane * CHUNK);
    {
        float4 c0 = xc4[0], c1 = xc4[1];
        #pragma unroll 1
        for (int i = 0; i < 16; i++) {
            int j = (i < 15) ? 2 * i + 2 : 30;
            float4 n0 = xc4[j], n1 = xc4[j + 1];
            float xs[8] = { c0.x, c0.y, c0.z, c0.w, c1.x, c1.y, c1.z, c1.w };
            float ys[8];
            #pragma unroll
            for (int k = 0; k < 8; k++) {
                float xk = xs[k];
                float acc0 = xk * om;
                float acc1 = 0.0f, acc2 = 0.0f, acc3 = 0.0f;
                #pragma unroll
                for (int n = 0; n < NS; n++) {
                    float wn = fmaf(A1[n], W[n], fmaf(A2[n], Wp[n], xk));
                    float& acc = (n & 3) == 0 ? acc0 : (n & 3) == 1 ? acc1
                               : (n & 3) == 2 ? acc2 : acc3;
                    acc = fmaf(B0[n], wn,   acc);
                    acc = fmaf(B1[n], W[n], acc);    // b1 * w[t-1]
                    Wp[n] = W[n]; W[n] = wn;
                }
                ys[k] = (acc0 + acc1) + (acc2 + acc3);
            }
            yc4[2 * i + 0] = make_float4(ys[0], ys[1], ys[2], ys[3]);
            yc4[2 * i + 1] = make_float4(ys[4], ys[5], ys[6], ys[7]);
            c0 = n0; c1 = n1;
        }
    }
}

extern "C" void kernel_launch(void* const* d_in, const int* in_sizes, int n_in,
                              void* d_out, int out_size)
{
    const float* x     = (const float*)d_in[0];
    const float* alpha = (const float*)d_in[1];
    const float* delta = (const float*)d_in[2];
    const float* theta = (const float*)d_in[3];
    const float* gamma = (const float*)d_in[4];
    const float* omega = (const float*)d_in[5];
    float* out = (float*)d_out;

    const int threads = 128;
    const int blocks  = (NCHAN * 32) / threads;   // 1024 blocks
    cema_kernel<<<blocks, threads>>>(x, alpha, delta, theta, gamma, omega, out);
}